// round 2
// baseline (speedup 1.0000x reference)
#include <cuda_runtime.h>
#include <cuda_bf16.h>

#define B_ 128
#define T_ 512
#define E_ 256
#define U_ 256

typedef unsigned long long u64t;

// 64MB scratch: xw[t][b][u]
__device__ __align__(16) float g_xw[T_ * B_ * U_];

__device__ __forceinline__ u64t ffma2(u64t a, u64t b, u64t c) {
    u64t d;
    asm("fma.rn.f32x2 %0, %1, %2, %3;" : "=l"(d) : "l"(a), "l"(b), "l"(c));
    return d;
}
__device__ __forceinline__ float f2lo(u64t v) { return __uint_as_float((unsigned)(v & 0xffffffffull)); }
__device__ __forceinline__ float f2hi(u64t v) { return __uint_as_float((unsigned)(v >> 32)); }
__device__ __forceinline__ u64t pk2(float lo, float hi) {
    u64t r;
    asm("mov.b64 %0, {%1, %2};" : "=l"(r) : "f"(lo), "f"(hi));
    return r;
}

// ---------------------------------------------------------------------------
// Phase 1: xw[t][b][u] = sum_e emb[sentence[b][t]][e] * W[u][e]
// GEMM M=65536 (r = t*128+b), N=256, K=256. Block: 64 rows x 256 u.
// 256 threads, thread tile 4 rows x 16 u (8 f32x2 pairs), BK=16.
// ---------------------------------------------------------------------------
__global__ void __launch_bounds__(256, 2)
xw_kernel(const int* __restrict__ sent, const float* __restrict__ emb,
          const float* __restrict__ Wm)
{
    __shared__ __align__(16) float As[16 * 65];   // [k][row], padded
    __shared__ __align__(16) float Bs[16 * 264];  // [k][u], padded
    __shared__ int idx[64];

    const int tid = threadIdx.x;
    const int r0 = blockIdx.x * 64;
    const int t  = r0 >> 7;       // 64-row tiles never cross t (128 rows per t)
    const int b0 = r0 & 127;

    if (tid < 64) idx[tid] = sent[(b0 + tid) * T_ + t];
    __syncthreads();

    const int tx = tid & 15;      // u-group: u = tx*16 .. +15
    const int ty = tid >> 4;      // row-group: rows ty*4 .. +3
    const int arow = tid >> 2;    // A-load row 0..63
    const int aq = tid & 3;       // A-load quad (4 floats)

    u64t acc[4][8];
    #pragma unroll
    for (int i = 0; i < 4; i++)
        #pragma unroll
        for (int p = 0; p < 8; p++) acc[i][p] = 0ull;

    for (int ko = 0; ko < 16; ko++) {
        // global loads first (overlap with previous compute)
        const float4 va = *(const float4*)(emb + (size_t)idx[arow] * E_ + ko * 16 + aq * 4);
        float4 vb[4];
        #pragma unroll
        for (int q = 0; q < 4; q++)
            vb[q] = *(const float4*)(Wm + (size_t)tid * E_ + ko * 16 + q * 4);

        __syncthreads();   // previous compute done before overwriting tiles

        As[(aq * 4 + 0) * 65 + arow] = va.x;
        As[(aq * 4 + 1) * 65 + arow] = va.y;
        As[(aq * 4 + 2) * 65 + arow] = va.z;
        As[(aq * 4 + 3) * 65 + arow] = va.w;
        #pragma unroll
        for (int q = 0; q < 4; q++) {
            Bs[(q * 4 + 0) * 264 + tid] = vb[q].x;
            Bs[(q * 4 + 1) * 264 + tid] = vb[q].y;
            Bs[(q * 4 + 2) * 264 + tid] = vb[q].z;
            Bs[(q * 4 + 3) * 264 + tid] = vb[q].w;
        }
        __syncthreads();

        #pragma unroll
        for (int k = 0; k < 16; k++) {
            const float a0 = As[k * 65 + ty * 4 + 0];
            const float a1 = As[k * 65 + ty * 4 + 1];
            const float a2 = As[k * 65 + ty * 4 + 2];
            const float a3 = As[k * 65 + ty * 4 + 3];
            const u64t ap0 = pk2(a0, a0), ap1 = pk2(a1, a1);
            const u64t ap2 = pk2(a2, a2), ap3 = pk2(a3, a3);
            const ulonglong2* bq = (const ulonglong2*)(Bs + k * 264 + tx * 16);
            const ulonglong2 x0 = bq[0], x1 = bq[1], x2 = bq[2], x3 = bq[3];
            const u64t bv[8] = {x0.x, x0.y, x1.x, x1.y, x2.x, x2.y, x3.x, x3.y};
            #pragma unroll
            for (int p = 0; p < 8; p++) {
                acc[0][p] = ffma2(bv[p], ap0, acc[0][p]);
                acc[1][p] = ffma2(bv[p], ap1, acc[1][p]);
                acc[2][p] = ffma2(bv[p], ap2, acc[2][p]);
                acc[3][p] = ffma2(bv[p], ap3, acc[3][p]);
            }
        }
    }

    #pragma unroll
    for (int i = 0; i < 4; i++) {
        const int rg = r0 + ty * 4 + i;
        ulonglong2* o = (ulonglong2*)(g_xw + (size_t)rg * U_ + tx * 16);
        o[0] = make_ulonglong2(acc[i][0], acc[i][1]);
        o[1] = make_ulonglong2(acc[i][2], acc[i][3]);
        o[2] = make_ulonglong2(acc[i][4], acc[i][5]);
        o[3] = make_ulonglong2(acc[i][6], acc[i][7]);
    }
}

// ---------------------------------------------------------------------------
// Phase 2: recurrence. Cluster of 2 CTAs handles one batch-pair (b0, b0+1).
// Each CTA holds a 128x256 half of U in registers (128 floats/thread,
// 256 threads) and computes its u-half for BOTH rows; halves are exchanged
// via remote STS + barrier.cluster each step.
// Thread map: uu = tid>>4 (8 u-rows each), ju = tid&15 (16-j chunk).
// Reduce over the 16 ju-lanes via shfl reduce-scatter: lane ju ends holding
// the dot for a = ju>>1 (pairs of lanes redundant -> both store, benign).
// ---------------------------------------------------------------------------
__device__ __forceinline__ float reduce16(const float v[8], int ju) {
    const unsigned FM = 0xffffffffu;
    float w[4];
    const bool t3 = (ju & 8) != 0;
    #pragma unroll
    for (int a = 0; a < 4; a++) {
        const float keep = t3 ? v[a + 4] : v[a];
        const float send = t3 ? v[a] : v[a + 4];
        w[a] = keep + __shfl_xor_sync(FM, send, 8);
    }
    float x[2];
    const bool t2 = (ju & 4) != 0;
    #pragma unroll
    for (int a = 0; a < 2; a++) {
        const float keep = t2 ? w[a + 2] : w[a];
        const float send = t2 ? w[a] : w[a + 2];
        x[a] = keep + __shfl_xor_sync(FM, send, 4);
    }
    const bool t1 = (ju & 2) != 0;
    const float keep = t1 ? x[1] : x[0];
    const float send = t1 ? x[0] : x[1];
    float y = keep + __shfl_xor_sync(FM, send, 2);
    y += __shfl_xor_sync(FM, y, 1);
    return y;   // lane ju holds dot for a = ju>>1
}

__global__ void __cluster_dims__(2, 1, 1) __launch_bounds__(256, 1)
rnn_kernel(const float* __restrict__ Um,
           const float* __restrict__ W1, const float* __restrict__ b1v,
           const float* __restrict__ W2, const float* __restrict__ b2v,
           float* __restrict__ outp)
{
    __shared__ __align__(16) float hbuf[2 * 2 * 256];  // [buf][b][u], full h mirrored per CTA
    __shared__ float hid[2][32];

    const int tid = threadIdx.x;
    unsigned rank;
    asm("mov.u32 %0, %%cluster_ctarank;" : "=r"(rank));
    const unsigned peer = rank ^ 1u;
    const int clu = blockIdx.x >> 1;
    const int b0 = clu * 2;
    const int b1i = b0 + 1;
    const int uhalf = (int)rank * 128;
    const int uu = tid >> 4;
    const int ju = tid & 15;
    const int jb = ju * 16;

    // U chunk into registers: rows u = uhalf + uu*8 + a, cols jb..jb+15
    u64t Ur[8][8];
    #pragma unroll
    for (int a = 0; a < 8; a++) {
        const u64t* p = (const u64t*)(Um + (size_t)(uhalf + uu * 8 + a) * U_ + jb);
        #pragma unroll
        for (int q = 0; q < 8; q++) Ur[a][q] = p[q];
    }

    for (int i = tid; i < 1024; i += 256) hbuf[i] = 0.0f;

    unsigned lbase = (unsigned)__cvta_generic_to_shared(hbuf);
    unsigned rbase;
    asm("mapa.shared::cluster.u32 %0, %1, %2;" : "=r"(rbase) : "r"(lbase), "r"(peer));

    const int u_g = uhalf + uu * 8 + (ju >> 1);

    // init barrier: peer's hbuf zero-init must complete before our remote writes
    asm volatile("barrier.cluster.arrive.aligned;" ::: "memory");
    asm volatile("barrier.cluster.wait.aligned;" ::: "memory");

    for (int t = 0; t < T_; t++) {
        const int rb = t & 1;
        const int wb = rb ^ 1;

        // xw for this step: issued early, consumed ~600 cyc later
        const float xw0 = __ldg(g_xw + (size_t)t * (B_ * U_) + b0  * U_ + u_g);
        const float xw1 = __ldg(g_xw + (size_t)t * (B_ * U_) + b1i * U_ + u_g);

        u64t h0[8], h1[8];
        const u64t* hp0 = (const u64t*)(hbuf + rb * 512 + jb);
        const u64t* hp1 = (const u64t*)(hbuf + rb * 512 + 256 + jb);
        #pragma unroll
        for (int q = 0; q < 8; q++) { h0[q] = hp0[q]; h1[q] = hp1[q]; }

        float s0[8], s1[8];
        #pragma unroll
        for (int a = 0; a < 8; a++) {
            u64t ac0 = 0ull, ac1 = 0ull;
            #pragma unroll
            for (int q = 0; q < 8; q++) {
                ac0 = ffma2(Ur[a][q], h0[q], ac0);
                ac1 = ffma2(Ur[a][q], h1[q], ac1);
            }
            s0[a] = f2lo(ac0) + f2hi(ac0);
            s1[a] = f2lo(ac1) + f2hi(ac1);
        }

        const float d0 = reduce16(s0, ju);
        const float d1 = reduce16(s1, ju);
        const float v0 = tanhf(d0 + xw0);
        const float v1 = tanhf(d1 + xw1);

        const int off0 = wb * 512 + u_g;
        const int off1 = wb * 512 + 256 + u_g;
        hbuf[off0] = v0;
        hbuf[off1] = v1;
        asm volatile("st.shared::cluster.f32 [%0], %1;" :: "r"(rbase + off0 * 4), "f"(v0) : "memory");
        asm volatile("st.shared::cluster.f32 [%0], %1;" :: "r"(rbase + off1 * 4), "f"(v1) : "memory");

        // release our writes / acquire peer's; also fences buffer reuse
        asm volatile("barrier.cluster.arrive.aligned;" ::: "memory");
        asm volatile("barrier.cluster.wait.aligned;" ::: "memory");
    }

    // Final h is in buf 0 (write buf of t=511 is (511+1)&1 = 0). Rank 1 exits
    // (its remote writes completed before the last barrier); rank 0 runs head.
    if (rank == 0) {
        for (int bi = 0; bi < 2; bi++) {
            if (tid < 32) {
                float acc = b1v[tid];
                const float* hr = hbuf + bi * 256;
                #pragma unroll 8
                for (int j = 0; j < 256; j++)
                    acc = fmaf(hr[j], __ldg(W1 + j * 32 + tid), acc);
                hid[bi][tid] = fmaxf(acc, 0.0f);
            }
        }
        __syncthreads();
        if (tid < 2) {
            float l0 = b2v[0], l1 = b2v[1];
            #pragma unroll
            for (int k = 0; k < 32; k++) {
                const float hv = hid[tid][k];
                l0 = fmaf(hv, __ldg(W2 + k * 2 + 0), l0);
                l1 = fmaf(hv, __ldg(W2 + k * 2 + 1), l1);
            }
            const float m = fmaxf(l0, l1);
            const float e0 = expf(l0 - m);
            const float e1 = expf(l1 - m);
            const float inv = 1.0f / (e0 + e1);
            outp[(b0 + tid) * 2 + 0] = e0 * inv;
            outp[(b0 + tid) * 2 + 1] = e1 * inv;
        }
    }
}

// ---------------------------------------------------------------------------
extern "C" void kernel_launch(void* const* d_in, const int* in_sizes, int n_in,
                              void* d_out, int out_size)
{
    const int*   sent = (const int*)d_in[0];
    const float* emb  = (const float*)d_in[1];
    const float* Wm   = (const float*)d_in[2];
    const float* Um   = (const float*)d_in[3];
    const float* W1   = (const float*)d_in[4];
    const float* b1v  = (const float*)d_in[5];
    const float* W2   = (const float*)d_in[6];
    const float* b2v  = (const float*)d_in[7];
    float* outp = (float*)d_out;
    (void)in_sizes; (void)n_in; (void)out_size;

    xw_kernel<<<1024, 256>>>(sent, emb, Wm);
    rnn_kernel<<<128, 256>>>(Um, W1, b1v, W2, b2v, outp);
}

// round 4
// speedup vs baseline: 1.6236x; 1.6236x over previous
#include <cuda_runtime.h>
#include <cuda_bf16.h>

#define B_ 128
#define T_ 512
#define E_ 256
#define U_ 256

typedef unsigned long long u64t;

// 64MB scratch: xw[t][b][u]
__device__ __align__(16) float g_xw[T_ * B_ * U_];

__device__ __forceinline__ u64t ffma2(u64t a, u64t b, u64t c) {
    u64t d;
    asm("fma.rn.f32x2 %0, %1, %2, %3;" : "=l"(d) : "l"(a), "l"(b), "l"(c));
    return d;
}
__device__ __forceinline__ float f2lo(u64t v) { return __uint_as_float((unsigned)(v & 0xffffffffull)); }
__device__ __forceinline__ float f2hi(u64t v) { return __uint_as_float((unsigned)(v >> 32)); }

__device__ __forceinline__ float tanh_fast(float x) {
    // 1 - 2/(exp(2x)+1): MUFU.EX2 + MUFU.RCP path; abs err ~5e-7, graceful at +-inf
    float ex = __expf(2.0f * x);
    return 1.0f - __fdividef(2.0f, ex + 1.0f);
}

// ---------------- mbarrier / cluster helpers ----------------
__device__ __forceinline__ void mbar_init(unsigned addr, unsigned cnt) {
    asm volatile("mbarrier.init.shared.b64 [%0], %1;" :: "r"(addr), "r"(cnt) : "memory");
}
__device__ __forceinline__ void mbar_expect(unsigned addr, unsigned bytes) {
    asm volatile("mbarrier.arrive.expect_tx.shared.b64 _, [%0], %1;"
                 :: "r"(addr), "r"(bytes) : "memory");
}
__device__ __forceinline__ void mbar_wait(unsigned addr, unsigned parity) {
    unsigned done;
    asm volatile(
        "{\n\t.reg .pred p;\n\t"
        "mbarrier.try_wait.parity.acquire.cta.shared::cta.b64 p, [%1], %2;\n\t"
        "selp.b32 %0, 1, 0, p;\n\t}"
        : "=r"(done) : "r"(addr), "r"(parity) : "memory");
    if (!done) {
        asm volatile(
            "{\n\t.reg .pred P1;\n\t"
            "W_%=:\n\t"
            "mbarrier.try_wait.parity.acquire.cta.shared::cta.b64 P1, [%0], %1, 0x989680;\n\t"
            "@P1 bra D_%=;\n\t"
            "bra W_%=;\n\t"
            "D_%=:\n\t}"
            :: "r"(addr), "r"(parity) : "memory");
    }
}
__device__ __forceinline__ void st_async_f32(unsigned raddr, float v, unsigned rbar) {
    asm volatile("st.async.shared::cluster.mbarrier::complete_tx::bytes.b32 [%0], %1, [%2];"
                 :: "r"(raddr), "r"(__float_as_uint(v)), "r"(rbar) : "memory");
}
__device__ __forceinline__ void cluster_sync_() {
    asm volatile("barrier.cluster.arrive.aligned;" ::: "memory");
    asm volatile("barrier.cluster.wait.aligned;" ::: "memory");
}

// ---------------------------------------------------------------------------
// Phase 1: xw[t][b][u] = sum_e emb[sentence[b][t]][e] * W[u][e]
// GEMM M=65536 (r=t*128+b), N=256, K=256. Block: 64 rows x 256 u, 256 thr.
// Thread tile: 4 rows (ty*4+i) x 16 u (q*64 + tx*4 + {0..3}, q=0..3).
// Software-pipelined global loads; conflict-free LDS layout; A pre-duplicated.
// ---------------------------------------------------------------------------
__global__ void __launch_bounds__(256)
xw_kernel(const int* __restrict__ sent, const float* __restrict__ emb,
          const float* __restrict__ Wm)
{
    __shared__ __align__(16) float2 As2[16 * 64];  // [k][row] duplicated pairs, 8KB
    __shared__ __align__(16) float  Bs[16 * 256];  // [k][u], 16KB
    __shared__ int idx[64];

    const int tid = threadIdx.x;
    const int r0 = blockIdx.x * 64;
    const int t  = r0 >> 7;
    const int b0 = r0 & 127;

    if (tid < 64) idx[tid] = sent[(b0 + tid) * T_ + t];
    __syncthreads();

    const int tx = tid & 15;
    const int ty = tid >> 4;
    const int arow = tid >> 2;
    const int aq = tid & 3;

    u64t acc[4][8];
    #pragma unroll
    for (int i = 0; i < 4; i++)
        #pragma unroll
        for (int p = 0; p < 8; p++) acc[i][p] = 0ull;

    // preload ko = 0
    float4 va = *(const float4*)(emb + (size_t)idx[arow] * E_ + aq * 4);
    float4 vb0 = *(const float4*)(Wm + (size_t)tid * E_ + 0);
    float4 vb1 = *(const float4*)(Wm + (size_t)tid * E_ + 4);
    float4 vb2 = *(const float4*)(Wm + (size_t)tid * E_ + 8);
    float4 vb3 = *(const float4*)(Wm + (size_t)tid * E_ + 12);

    for (int ko = 0; ko < 16; ko++) {
        if (ko > 0) __syncthreads();  // prior compute reads done

        As2[(aq * 4 + 0) * 64 + arow] = make_float2(va.x, va.x);
        As2[(aq * 4 + 1) * 64 + arow] = make_float2(va.y, va.y);
        As2[(aq * 4 + 2) * 64 + arow] = make_float2(va.z, va.z);
        As2[(aq * 4 + 3) * 64 + arow] = make_float2(va.w, va.w);
        // transpose-store W: Bs[k][u=tid]
        {
            const float v[16] = {vb0.x, vb0.y, vb0.z, vb0.w, vb1.x, vb1.y, vb1.z, vb1.w,
                                 vb2.x, vb2.y, vb2.z, vb2.w, vb3.x, vb3.y, vb3.z, vb3.w};
            #pragma unroll
            for (int j = 0; j < 16; j++) Bs[j * 256 + tid] = v[j];
        }
        __syncthreads();

        // issue NEXT iteration's global loads before compute (latency hidden)
        if (ko < 15) {
            const int kb = (ko + 1) * 16;
            va  = *(const float4*)(emb + (size_t)idx[arow] * E_ + kb + aq * 4);
            vb0 = *(const float4*)(Wm + (size_t)tid * E_ + kb + 0);
            vb1 = *(const float4*)(Wm + (size_t)tid * E_ + kb + 4);
            vb2 = *(const float4*)(Wm + (size_t)tid * E_ + kb + 8);
            vb3 = *(const float4*)(Wm + (size_t)tid * E_ + kb + 12);
        }

        #pragma unroll
        for (int k = 0; k < 16; k++) {
            u64t ap[4];
            #pragma unroll
            for (int i = 0; i < 4; i++)
                ap[i] = *(const u64t*)&As2[k * 64 + ty * 4 + i];
            #pragma unroll
            for (int q = 0; q < 4; q++) {
                // 16 contiguous 16B chunks across tx -> conflict-free LDS.128
                const ulonglong2 bq = *(const ulonglong2*)&Bs[k * 256 + q * 64 + tx * 4];
                #pragma unroll
                for (int i = 0; i < 4; i++) {
                    acc[i][2 * q + 0] = ffma2(bq.x, ap[i], acc[i][2 * q + 0]);
                    acc[i][2 * q + 1] = ffma2(bq.y, ap[i], acc[i][2 * q + 1]);
                }
            }
        }
    }

    #pragma unroll
    for (int i = 0; i < 4; i++) {
        const int rg = r0 + ty * 4 + i;
        #pragma unroll
        for (int q = 0; q < 4; q++) {
            float4 o;
            o.x = f2lo(acc[i][2 * q + 0]); o.y = f2hi(acc[i][2 * q + 0]);
            o.z = f2lo(acc[i][2 * q + 1]); o.w = f2hi(acc[i][2 * q + 1]);
            __stcs((float4*)(g_xw + (size_t)rg * U_ + q * 64 + tx * 4), o);
        }
    }
}

// ---------------------------------------------------------------------------
// Phase 2: recurrence. Cluster of 2 CTAs per batch-pair; U half in registers.
// Per-step sync = st.async(tx)->peer mbarrier + local bar.sync (replaces the
// ~490-cyc barrier.cluster). xw[t+1] prefetched a full step ahead.
// ---------------------------------------------------------------------------
__device__ __forceinline__ float reduce16(const float v[8], int ju) {
    const unsigned FM = 0xffffffffu;
    float w[4];
    const bool t3 = (ju & 8) != 0;
    #pragma unroll
    for (int a = 0; a < 4; a++) {
        const float keep = t3 ? v[a + 4] : v[a];
        const float send = t3 ? v[a] : v[a + 4];
        w[a] = keep + __shfl_xor_sync(FM, send, 8);
    }
    float x[2];
    const bool t2 = (ju & 4) != 0;
    #pragma unroll
    for (int a = 0; a < 2; a++) {
        const float keep = t2 ? w[a + 2] : w[a];
        const float send = t2 ? w[a] : w[a + 2];
        x[a] = keep + __shfl_xor_sync(FM, send, 4);
    }
    const bool t1 = (ju & 2) != 0;
    const float keep = t1 ? x[1] : x[0];
    const float send = t1 ? x[0] : x[1];
    float y = keep + __shfl_xor_sync(FM, send, 2);
    y += __shfl_xor_sync(FM, y, 1);
    return y;   // lane ju holds dot for a = ju>>1
}

__global__ void __cluster_dims__(2, 1, 1) __launch_bounds__(256, 1)
rnn_kernel(const float* __restrict__ Um,
           const float* __restrict__ W1, const float* __restrict__ b1v,
           const float* __restrict__ W2, const float* __restrict__ b2v,
           float* __restrict__ outp)
{
    __shared__ __align__(16) float hbuf[2 * 2 * 256];   // [buf][b][u]
    __shared__ __align__(8)  unsigned long long fullbar[2];
    __shared__ float hid[2][32];

    const int tid = threadIdx.x;
    unsigned rank;
    asm("mov.u32 %0, %%cluster_ctarank;" : "=r"(rank));
    const unsigned peer = rank ^ 1u;
    const int b0 = (blockIdx.x >> 1) * 2;
    const int b1i = b0 + 1;
    const int uhalf = (int)rank * 128;
    const int uu = tid >> 4;
    const int ju = tid & 15;
    const int jb = ju * 16;

    // U chunk into registers: rows u = uhalf + uu*8 + a, cols jb..jb+15
    u64t Ur[8][8];
    #pragma unroll
    for (int a = 0; a < 8; a++) {
        const u64t* p = (const u64t*)(Um + (size_t)(uhalf + uu * 8 + a) * U_ + jb);
        #pragma unroll
        for (int q = 0; q < 8; q++) Ur[a][q] = p[q];
    }

    for (int i = tid; i < 1024; i += 256) hbuf[i] = 0.0f;

    const unsigned lh = (unsigned)__cvta_generic_to_shared(hbuf);
    const unsigned lb = (unsigned)__cvta_generic_to_shared(fullbar);
    unsigned rh, rb_;
    asm("mapa.shared::cluster.u32 %0, %1, %2;" : "=r"(rh)  : "r"(lh), "r"(peer));
    asm("mapa.shared::cluster.u32 %0, %1, %2;" : "=r"(rb_) : "r"(lb), "r"(peer));

    if (tid == 0) {
        mbar_init(lb + 0, 1);
        mbar_init(lb + 8, 1);
        mbar_expect(lb + 8, 2048);   // arm full[1] for phase 0 (peer's t=0 txs)
    }
    __syncthreads();
    cluster_sync_();                 // peer's init visible before any st.async

    const int u_g = uhalf + uu * 8 + (ju >> 1);
    unsigned ph0 = 0, ph1 = 0;

    float cxw0 = __ldcs(g_xw + (size_t)b0  * U_ + u_g);
    float cxw1 = __ldcs(g_xw + (size_t)b1i * U_ + u_g);

    for (int t = 0; t < T_; t++) {
        const int rbuf = t & 1;
        const int wbuf = rbuf ^ 1;

        if (t > 0) {
            if (rbuf == 0) { mbar_wait(lb + 0, ph0); ph0 ^= 1u; }
            else           { mbar_wait(lb + 8, ph1); ph1 ^= 1u; }
        }
        if (tid == 0) mbar_expect(lb + rbuf * 8, 2048);  // re-arm for next phase

        // prefetch next step's xw (consumed next iteration)
        const int tn = (t + 1 < T_) ? t + 1 : t;
        const float nxw0 = __ldcs(g_xw + (size_t)tn * (B_ * U_) + b0  * U_ + u_g);
        const float nxw1 = __ldcs(g_xw + (size_t)tn * (B_ * U_) + b1i * U_ + u_g);

        u64t h0[8], h1[8];
        const u64t* hp0 = (const u64t*)(hbuf + rbuf * 512 + jb);
        const u64t* hp1 = (const u64t*)(hbuf + rbuf * 512 + 256 + jb);
        #pragma unroll
        for (int q = 0; q < 8; q++) { h0[q] = hp0[q]; h1[q] = hp1[q]; }

        float s0[8], s1[8];
        #pragma unroll
        for (int a = 0; a < 8; a++) {
            u64t ac0 = 0ull, ac1 = 0ull;
            #pragma unroll
            for (int q = 0; q < 8; q++) {
                ac0 = ffma2(Ur[a][q], h0[q], ac0);
                ac1 = ffma2(Ur[a][q], h1[q], ac1);
            }
            s0[a] = f2lo(ac0) + f2hi(ac0);
            s1[a] = f2lo(ac1) + f2hi(ac1);
        }

        const float d0 = reduce16(s0, ju);
        const float d1 = reduce16(s1, ju);
        const float v0 = tanh_fast(d0 + cxw0);
        const float v1 = tanh_fast(d1 + cxw1);

        const int off0 = wbuf * 512 + u_g;
        const int off1 = wbuf * 512 + 256 + u_g;
        hbuf[off0] = v0;
        hbuf[off1] = v1;
        st_async_f32(rh + off0 * 4, v0, rb_ + wbuf * 8);
        st_async_f32(rh + off1 * 4, v1, rb_ + wbuf * 8);

        __syncthreads();   // local-half visibility for next step's reads
        cxw0 = nxw0; cxw1 = nxw1;
    }

    // final h is in buf 0; wait for peer's last txs, then local barrier
    mbar_wait(lb + 0, ph0);
    __syncthreads();

    if (rank == 0) {
        if (tid < 32) {
            for (int bi = 0; bi < 2; bi++) {
                float acc = b1v[tid];
                const float* hr = hbuf + bi * 256;
                #pragma unroll 8
                for (int j = 0; j < 256; j++)
                    acc = fmaf(hr[j], __ldg(W1 + j * 32 + tid), acc);
                hid[bi][tid] = fmaxf(acc, 0.0f);
            }
        }
        __syncthreads();
        if (tid < 2) {
            float l0 = b2v[0], l1 = b2v[1];
            #pragma unroll
            for (int k = 0; k < 32; k++) {
                const float hv = hid[tid][k];
                l0 = fmaf(hv, __ldg(W2 + k * 2 + 0), l0);
                l1 = fmaf(hv, __ldg(W2 + k * 2 + 1), l1);
            }
            const float m = fmaxf(l0, l1);
            const float e0 = expf(l0 - m);
            const float e1 = expf(l1 - m);
            const float inv = 1.0f / (e0 + e1);
            outp[(b0 + tid) * 2 + 0] = e0 * inv;
            outp[(b0 + tid) * 2 + 1] = e1 * inv;
        }
    }
    cluster_sync_();   // no CTA exits while peer traffic could be in flight
}

// ---------------------------------------------------------------------------
extern "C" void kernel_launch(void* const* d_in, const int* in_sizes, int n_in,
                              void* d_out, int out_size)
{
    const int*   sent = (const int*)d_in[0];
    const float* emb  = (const float*)d_in[1];
    const float* Wm   = (const float*)d_in[2];
    const float* Um   = (const float*)d_in[3];
    const float* W1   = (const float*)d_in[4];
    const float* b1v  = (const float*)d_in[5];
    const float* W2   = (const float*)d_in[6];
    const float* b2v  = (const float*)d_in[7];
    float* outp = (float*)d_out;
    (void)in_sizes; (void)n_in; (void)out_size;

    xw_kernel<<<1024, 256>>>(sent, emb, Wm);
    rnn_kernel<<<128, 256>>>(Um, W1, b1v, W2, b2v, outp);
}